// round 11
// baseline (speedup 1.0000x reference)
#include <cuda_runtime.h>
#include <cstdint>
#include <cstddef>

// Problem constants (fixed by the dataset)
#define B_  32
#define N_  1024
#define D_  128
#define C_  16
// P*P = 16, Hg = 32, out image 128x128 per (b,c)

// Pipelined persistent tiling: grid = 128 CTAs x 256 threads.
// Each CTA processes 4 chunks of 64 rows (chunk ids bid, bid+128, +256, +384),
// double-buffered smem, one cp.async group per chunk.
#define THREADS   256
#define GRID      128
#define PER_CTA   4
#define CHUNK     64

// Shared layout (floats)
#define BUF_OFF   0                     // [2][64*128] x chunks, swizzled (64KB)
#define SW_OFF    (2 * CHUNK * D_)      // 16384: [16][128] W, swizzled (8KB)
#define TAB_OFF   (SW_OFF + 16 * D_)    // 18432: [2][272] per-chunk cbm+mask
#define SMEM_FLOATS (TAB_OFF + 2 * 272) // 18976
#define SMEM_BYTES  (SMEM_FLOATS * 4)   // 75904

// Precomputed channel table: cb[c*16+p] = emb[c]·W[p] + bias[p]
__device__ float g_cb[C_ * 16];

__device__ __forceinline__ uint32_t smem_u32(const void* p) {
    return (uint32_t)__cvta_generic_to_shared(p);
}

// Blackwell packed fp32x2 FMA (PTX-only)
#define FMA_F32X2(d, a, b, c) \
    asm("fma.rn.f32x2 %0, %1, %2, %3;" : "=l"(d) : "l"(a), "l"(b), "l"(c))

// ---------------------------------------------------------------------------
// Kernel A: build the 16x16 channel table once (one warp per entry).
// ---------------------------------------------------------------------------
__global__ void __launch_bounds__(1024, 1)
cb_table_kernel(const float* __restrict__ emb,   // [256, D]
                const float* __restrict__ W,     // [16, D]
                const float* __restrict__ bias)  // [16]
{
    const int w = (blockIdx.x * blockDim.x + threadIdx.x) >> 5;  // 0..255
    const int l = threadIdx.x & 31;
    const int c = w >> 4, p = w & 15;

    float4 e = *reinterpret_cast<const float4*>(emb + (size_t)c * D_ + l * 4);
    float4 v = *reinterpret_cast<const float4*>(W   + (size_t)p * D_ + l * 4);
    float s = e.x * v.x + e.y * v.y + e.z * v.z + e.w * v.w;
    #pragma unroll
    for (int off = 16; off > 0; off >>= 1)
        s += __shfl_xor_sync(0xffffffffu, s, off);
    if (l == 0) g_cb[w] = s + bias[p];
}

// Issue the cp.async burst for one 64-row chunk (32KB contiguous), swizzled.
__device__ __forceinline__ void stage_chunk(float* dstbuf, const float* x,
                                            int chunk, int t)
{
    const float4* gx = reinterpret_cast<const float4*>(x + (size_t)chunk * CHUNK * D_);
    #pragma unroll
    for (int i = 0; i < 8; ++i) {
        int k = t + THREADS * i;                 // 0..2047: row = k>>5, col16 = k&31
        int row = k >> 5, col = k & 31;
        uint32_t dst = smem_u32(dstbuf + row * D_ + ((col ^ (row & 7)) << 2));
        asm volatile("cp.async.cg.shared.global [%0], [%1], 16;\n"
                     :: "r"(dst), "l"(gx + k));
    }
}

// Build the mask-premultiplied channel table for batch b into tb[272].
__device__ __forceinline__ void build_table(float* tb, const float* pmask,
                                            int b, int t)
{
    tb[t] = g_cb[t] * pmask[b * C_ + (t >> 4)];
    if (t < C_) tb[256 + t] = pmask[b * C_ + t];
}

// ---------------------------------------------------------------------------
// Kernel B: pipelined main decode.
// ---------------------------------------------------------------------------
__global__ void __launch_bounds__(THREADS, 2)
QBD_main_kernel(
    const float* __restrict__ x,     // [B, N, D]
    const float* __restrict__ pmask, // [B, C]
    const float* __restrict__ W,     // [16, D]
    float* __restrict__ out)         // [B, C, 128, 128]
{
    extern __shared__ float sm[];
    float* bufs = sm + BUF_OFF;      // two 8192-float chunk buffers
    float* sw   = sm + SW_OFF;
    float* tabs = sm + TAB_OFF;      // two 272-float tables

    const int t   = threadIdx.x;
    const int bid = blockIdx.x;

    // ---- Prologue: group G0 = W + chunk(bid) into buf0; table for chunk0 ----
    stage_chunk(bufs, x, bid, t);
    const float4* gw = reinterpret_cast<const float4*>(W);
    #pragma unroll
    for (int i = 0; i < 2; ++i) {
        int k = t + THREADS * i;                 // 0..511
        int wrow = k >> 5, col = k & 31;
        uint32_t dst = smem_u32(sw + wrow * D_ + ((col ^ (wrow & 7)) << 2));
        asm volatile("cp.async.cg.shared.global [%0], [%1], 16;\n"
                     :: "r"(dst), "l"(gw + k));
    }
    asm volatile("cp.async.commit_group;\n");
    build_table(tabs, pmask, bid >> 4, t);

    const int row = t & 63;
    const int q   = t >> 6;                      // warp-uniform patch row
    const int xs  = row & 7;

    #pragma unroll
    for (int k = 0; k < PER_CTA; ++k) {
        const int chunk = bid + GRID * k;
        const int p     = k & 1;
        float* buf = bufs + p * (CHUNK * D_);
        float* tb  = tabs + p * 272;

        // Barrier A: all warps finished reading buf[p^1] (chunk k-1) -> safe
        // to overwrite it with chunk k+1's data.
        __syncthreads();

        if (k + 1 < PER_CTA) {
            stage_chunk(bufs + (p ^ 1) * (CHUNK * D_), x, bid + GRID * (k + 1), t);
            asm volatile("cp.async.commit_group;\n");
            // Pending groups: {G_k, G_{k+1}} -> allow 1 pending => G_k complete.
            asm volatile("cp.async.wait_group 1;\n");
        } else {
            asm volatile("cp.async.wait_group 0;\n");
        }
        // Barrier B: chunk k's data (copied by all threads) visible to all.
        __syncthreads();

        // Table for the NEXT chunk (different batch) into the other slot;
        // overlaps the in-flight loads. Read next iter after barriers.
        if (k + 1 < PER_CTA)
            build_table(tabs + (p ^ 1) * 272, pmask, (bid + GRID * (k + 1)) >> 4, t);

        // ---- Compute chunk k: xa[row][q*4+jj] (R6 mapping: wv broadcast,
        //      xv conflict-free 4-phase floor) ----
        const float* xr = buf + row * D_;
        unsigned long long acc2[4] = {0ull, 0ull, 0ull, 0ull};

        #pragma unroll
        for (int d4 = 0; d4 < 32; ++d4) {
            ulonglong2 xv = *reinterpret_cast<const ulonglong2*>(xr + ((d4 ^ xs) << 2));
            #pragma unroll
            for (int jj = 0; jj < 4; ++jj) {
                const int j = q * 4 + jj;        // warp-uniform
                const ulonglong2 wv = *reinterpret_cast<const ulonglong2*>(
                    sw + j * D_ + ((d4 ^ (j & 7)) << 2));
                FMA_F32X2(acc2[jj], xv.x, wv.x, acc2[jj]);
                FMA_F32X2(acc2[jj], xv.y, wv.y, acc2[jj]);
            }
        }

        // Horizontal add (even+odd d), re-pack for packed epilogue
        float xa[4];
        #pragma unroll
        for (int jj = 0; jj < 4; ++jj) {
            uint32_t lo, hi;
            asm("mov.b64 {%0, %1}, %2;" : "=r"(lo), "=r"(hi) : "l"(acc2[jj]));
            xa[jj] = __uint_as_float(lo) + __uint_as_float(hi);
        }
        unsigned long long xa2[2];
        #pragma unroll
        for (int kk = 0; kk < 2; ++kk)
            asm("mov.b64 %0, {%1, %2};" : "=l"(xa2[kk])
                : "r"(__float_as_uint(xa[2 * kk])), "r"(__float_as_uint(xa[2 * kk + 1])));

        // ---- Epilogue: 1 STG.128 per channel; warp = 32 consecutive n,
        //      same hg & q -> contiguous 512B line per (warp, c). ----
        const int n  = chunk * CHUNK + row;      // global token id
        const int b  = n >> 10;
        const int nn = n & 1023;
        const int hg = nn >> 5, wg = nn & 31;
        float* ob = out + (size_t)b * (C_ * 128 * 128) + (hg * 4 + q) * 128 + wg * 4;

        #pragma unroll
        for (int c = 0; c < C_; ++c) {
            float m = tb[256 + c];
            unsigned long long m2;
            asm("mov.b64 %0, {%1, %1};" : "=l"(m2) : "r"(__float_as_uint(m)));
            ulonglong2 cb = *reinterpret_cast<const ulonglong2*>(tb + c * 16 + q * 4);
            ulonglong2 v;
            FMA_F32X2(v.x, xa2[0], m2, cb.x);
            FMA_F32X2(v.y, xa2[1], m2, cb.y);
            *reinterpret_cast<ulonglong2*>(ob + c * (128 * 128)) = v;
        }
    }
}

extern "C" void kernel_launch(void* const* d_in, const int* in_sizes, int n_in,
                              void* d_out, int out_size)
{
    const float* x    = (const float*)d_in[0];  // [32,1024,128]
    const float* pm   = (const float*)d_in[1];  // [32,16]
    const float* emb  = (const float*)d_in[2];  // [256,128]
    const float* W    = (const float*)d_in[3];  // [16,128]
    const float* bias = (const float*)d_in[4];  // [16]
    float* out        = (float*)d_out;          // [32,16,128,128]

    // Kernel A: 256-entry channel table (one warp per entry)
    cb_table_kernel<<<8, 1024>>>(emb, W, bias);

    // Kernel B: pipelined persistent decode
    cudaFuncSetAttribute(QBD_main_kernel,
                         cudaFuncAttributeMaxDynamicSharedMemorySize, SMEM_BYTES);
    QBD_main_kernel<<<GRID, THREADS, SMEM_BYTES>>>(x, pm, W, out);
}